// round 8
// baseline (speedup 1.0000x reference)
#include <cuda_runtime.h>
#include <cstdint>

// BSplineBasis, uniform knots, truncated-power form, PACKED f32x2 math.
// Each thread owns 2 adjacent splines; the 8-entry polynomial table is packed
// lane-wise into 64-bit register pairs. relu(d) = (d + |d|) with the /2^3
// folded into E_j/8 (exact). Global I/O is LDG.64 / STG.64.
// x: (4096,4096) f32, coefficients: (4096,8) f32, grid: (12,) f32 uniform.

#define S_TOTAL 4096
#define B_TOTAL 4096
#define THREADS 256
#define SPT     2
#define TILE_S  (THREADS * SPT)       // 512 splines/block
#define GRID_X  (S_TOTAL / TILE_S)    // 8
#define GRID_Y  256
#define ROWS    (B_TOTAL / GRID_Y)    // 16
#define UN      8                     // rows in flight (MLP)

__device__ __forceinline__ uint64_t pk2(float lo, float hi) {
    uint64_t r; asm("mov.b64 %0, {%1, %2};" : "=l"(r) : "f"(lo), "f"(hi)); return r;
}
__device__ __forceinline__ uint64_t fma2(uint64_t a, uint64_t b, uint64_t c) {
    uint64_t d; asm("fma.rn.f32x2 %0, %1, %2, %3;" : "=l"(d) : "l"(a), "l"(b), "l"(c)); return d;
}
__device__ __forceinline__ uint64_t add2(uint64_t a, uint64_t b) {
    uint64_t d; asm("add.rn.f32x2 %0, %1, %2;" : "=l"(d) : "l"(a), "l"(b)); return d;
}
__device__ __forceinline__ uint64_t mul2(uint64_t a, uint64_t b) {
    uint64_t d; asm("mul.rn.f32x2 %0, %1, %2;" : "=l"(d) : "l"(a), "l"(b)); return d;
}

__global__ __launch_bounds__(THREADS)
void bspline_kernel(const float* __restrict__ x,
                    const float* __restrict__ coeff,
                    const float* __restrict__ grid,
                    float* __restrict__ out)
{
    const int t  = threadIdx.x;
    const int s0 = blockIdx.x * TILE_S + t * SPT;

    // ---- Build packed truncated-power table (lane0 = spline s0, lane1 = s0+1) ----
    float Ar[2], Br[2], Cr[2], Dr[2], Er[2][4];
    #pragma unroll
    for (int j = 0; j < SPT; j++) {
        const float4* crow = reinterpret_cast<const float4*>(coeff + (size_t)(s0 + j) * 8);
        float4 qa = crow[0], qb = crow[1];
        float c8[8] = {qa.x, qa.y, qa.z, qa.w, qb.x, qb.y, qb.z, qb.w};
        float pd[5];
        #pragma unroll
        for (int w = 0; w < 5; w++)
            pd[w] = (c8[w+3] - c8[w] + 3.0f * (c8[w+1] - c8[w+2])) * (1.0f / 6.0f);
        Ar[j] = (c8[0] + 4.0f * c8[1] + c8[2]) * (1.0f / 6.0f);
        Br[j] = (c8[2] - c8[0]) * 0.5f;
        Cr[j] = (c8[0] - 2.0f * c8[1] + c8[2]) * 0.5f;
        Dr[j] = pd[0];
        #pragma unroll
        for (int e = 0; e < 4; e++)
            Er[j][e] = (pd[e+1] - pd[e]) * 0.125f;   // /8 folds the relu half^3
    }
    const uint64_t A2 = pk2(Ar[0], Ar[1]);
    const uint64_t B2 = pk2(Br[0], Br[1]);
    const uint64_t C2 = pk2(Cr[0], Cr[1]);
    const uint64_t D2 = pk2(Dr[0], Dr[1]);
    uint64_t E2[4];
    #pragma unroll
    for (int e = 0; e < 4; e++) E2[e] = pk2(Er[0][e], Er[1][e]);

    const float gstart = __ldg(&grid[3]);
    const float invh   = 1.0f / (__ldg(&grid[1]) - __ldg(&grid[0]));
    const float c0     = -gstart * invh;               // y = x*invh + c0, in [0,5)
    const uint64_t invh2 = pk2(invh, invh);
    const uint64_t c02   = pk2(c0, c0);
    uint64_t MJ[4];
    #pragma unroll
    for (int e = 0; e < 4; e++) MJ[e] = pk2(-(float)(e + 1), -(float)(e + 1));
    const uint64_t ABSM = 0x7FFFFFFF7FFFFFFFull;

    const int b0 = blockIdx.y * ROWS;
    const char* xp = reinterpret_cast<const char*>(x + (size_t)b0 * S_TOTAL + s0);
    char*       op = reinterpret_cast<char*>(out + (size_t)b0 * S_TOTAL + s0);
    const size_t rstride = (size_t)S_TOTAL * sizeof(float);

    #pragma unroll 1
    for (int r = 0; r < ROWS; r += UN) {
        uint64_t xv[UN];
        #pragma unroll
        for (int k = 0; k < UN; k++)
            xv[k] = *reinterpret_cast<const uint64_t*>(xp + (size_t)k * rstride);

        #pragma unroll
        for (int k = 0; k < UN; k++) {
            uint64_t y = fma2(xv[k], invh2, c02);

            // Base cubic (Horner), both lanes at once
            uint64_t v = fma2(fma2(fma2(D2, y, C2), y, B2), y, A2);

            // Truncated cubic corrections: relu(d) = d + |d| (scale in E)
            #pragma unroll
            for (int e = 0; e < 4; e++) {
                uint64_t d  = add2(y, MJ[e]);
                uint64_t rr = add2(d, d & ABSM);
                uint64_t q  = mul2(rr, rr);
                v = fma2(E2[e], mul2(q, rr), v);
            }

            *reinterpret_cast<uint64_t*>(op + (size_t)k * rstride) = v;
        }
        xp += (size_t)UN * rstride;
        op += (size_t)UN * rstride;
    }
}

extern "C" void kernel_launch(void* const* d_in, const int* in_sizes, int n_in,
                              void* d_out, int out_size)
{
    const float* x     = (const float*)d_in[0];
    const float* coeff = (const float*)d_in[1];
    const float* grid  = (const float*)d_in[2];
    float*       out   = (float*)d_out;

    dim3 g(GRID_X, GRID_Y);   // (8, 256) = 2048 blocks
    bspline_kernel<<<g, THREADS>>>(x, coeff, grid, out);
}

// round 10
// speedup vs baseline: 1.2821x; 1.2821x over previous
#include <cuda_runtime.h>
#include <cuda_bf16.h>

// BSplineBasis, uniform knots, truncated-power form (C^2 exact), software-
// pipelined: double-buffered row batches keep 8 LDGs in flight during compute.
//   y = (x - grid[3]) / h in [0,5)
//   out = A + B y + C y^2 + D y^3 + sum_{j=1..4} E_j * max(0, y-j)^3
// x: (4096,4096) f32, coefficients: (4096,8) f32, grid: (12,) f32 uniform.

#define S_TOTAL 4096
#define B_TOTAL 4096
#define THREADS 256
#define GRID_X  (S_TOTAL / THREADS)   // 16
#define GRID_Y  128
#define ROWS    (B_TOTAL / GRID_Y)    // 32
#define UN      8                     // rows per buffer (MLP)

__global__ __launch_bounds__(THREADS)
void bspline_kernel(const float* __restrict__ x,
                    const float* __restrict__ coeff,
                    const float* __restrict__ grid,
                    float* __restrict__ out)
{
    const int t = threadIdx.x;
    const int s = blockIdx.x * THREADS + t;

    // ---- Build truncated-power table in registers ----
    const float4* crow = reinterpret_cast<const float4*>(coeff + (size_t)s * 8);
    float4 Aq = crow[0], Bq = crow[1];
    float c8[8] = {Aq.x, Aq.y, Aq.z, Aq.w, Bq.x, Bq.y, Bq.z, Bq.w};

    float pd[5];
    #pragma unroll
    for (int w = 0; w < 5; w++)
        pd[w] = (c8[w+3] - c8[w] + 3.0f * (c8[w+1] - c8[w+2])) * (1.0f / 6.0f);

    const float A = (c8[0] + 4.0f * c8[1] + c8[2]) * (1.0f / 6.0f);
    const float B = (c8[2] - c8[0]) * 0.5f;
    const float C = (c8[0] - 2.0f * c8[1] + c8[2]) * 0.5f;
    const float D = pd[0];
    const float E1 = pd[1] - pd[0];
    const float E2 = pd[2] - pd[1];
    const float E3 = pd[3] - pd[2];
    const float E4 = pd[4] - pd[3];

    const float gstart = __ldg(&grid[3]);
    const float invh   = 1.0f / (__ldg(&grid[1]) - __ldg(&grid[0]));
    const float c0     = -gstart * invh;                 // y = x*invh + c0

    const int b0 = blockIdx.y * ROWS;
    const float* xp = x   + (size_t)b0 * S_TOTAL + s;
    float*       op = out + (size_t)b0 * S_TOTAL + s;

    float bufA[UN], bufB[UN];

    // Prologue: first batch in flight
    #pragma unroll
    for (int k = 0; k < UN; k++)
        bufA[k] = xp[(size_t)k * S_TOTAL];

    #pragma unroll 1
    for (int r = 0; r < ROWS; r += 2 * UN) {
        // Prefetch batch B (rows r+UN) — overlaps compute of batch A
        #pragma unroll
        for (int k = 0; k < UN; k++)
            bufB[k] = xp[(size_t)(UN + k) * S_TOTAL];

        // Compute + store batch A (rows r)
        #pragma unroll
        for (int k = 0; k < UN; k++) {
            float y = fmaf(bufA[k], invh, c0);
            float v = fmaf(fmaf(fmaf(D, y, C), y, B), y, A);
            float r1 = fmaxf(y - 1.0f, 0.0f);
            float r2 = fmaxf(y - 2.0f, 0.0f);
            float r3 = fmaxf(y - 3.0f, 0.0f);
            float r4 = fmaxf(y - 4.0f, 0.0f);
            v = fmaf(E1, r1 * r1 * r1, v);
            v = fmaf(E2, r2 * r2 * r2, v);
            v = fmaf(E3, r3 * r3 * r3, v);
            v = fmaf(E4, r4 * r4 * r4, v);
            op[(size_t)k * S_TOTAL] = v;
        }

        // Prefetch next batch A (rows r+2*UN) — overlaps compute of batch B
        if (r + 2 * UN < ROWS) {
            #pragma unroll
            for (int k = 0; k < UN; k++)
                bufA[k] = xp[(size_t)(2 * UN + k) * S_TOTAL];
        }

        // Compute + store batch B (rows r+UN)
        #pragma unroll
        for (int k = 0; k < UN; k++) {
            float y = fmaf(bufB[k], invh, c0);
            float v = fmaf(fmaf(fmaf(D, y, C), y, B), y, A);
            float r1 = fmaxf(y - 1.0f, 0.0f);
            float r2 = fmaxf(y - 2.0f, 0.0f);
            float r3 = fmaxf(y - 3.0f, 0.0f);
            float r4 = fmaxf(y - 4.0f, 0.0f);
            v = fmaf(E1, r1 * r1 * r1, v);
            v = fmaf(E2, r2 * r2 * r2, v);
            v = fmaf(E3, r3 * r3 * r3, v);
            v = fmaf(E4, r4 * r4 * r4, v);
            op[(size_t)(UN + k) * S_TOTAL] = v;
        }

        xp += (size_t)(2 * UN) * S_TOTAL;
        op += (size_t)(2 * UN) * S_TOTAL;
    }
}

extern "C" void kernel_launch(void* const* d_in, const int* in_sizes, int n_in,
                              void* d_out, int out_size)
{
    const float* x     = (const float*)d_in[0];
    const float* coeff = (const float*)d_in[1];
    const float* grid  = (const float*)d_in[2];
    float*       out   = (float*)d_out;

    dim3 g(GRID_X, GRID_Y);   // (16, 128) = 2048 blocks
    bspline_kernel<<<g, THREADS>>>(x, coeff, grid, out);
}